// round 14
// baseline (speedup 1.0000x reference)
#include <cuda_runtime.h>
#include <cstdint>

// Problem constants
#define BATCH   1024
#define IN_H    128
#define IN_W    128
#define WPAD    132
#define NKW     25
#define NK      625
#define KHW     100

// Tiling
#define IGROUPS 5           // blockIdx.y: groups of 5 output rows
#define KL      125         // outputs per block (5 rows * 25 cols)
#define XROWS   30          // padded input rows per 5 output rows
#define XS      164         // x smem row stride (words), mult of 4.
                            //  Within a warp (32 consecutive kl, one image):
                            //  bank = (12*il + 5*jj) mod 32; same-il distinct,
                            //  il-boundary collision needs dkl=53>32 -> NONE.
#define IMGW    (XROWS*XS)  // 4920 words per image tile
#define HB      3           // images per group (one per 128-thread slice)
#define BUFW    (HB*IMGW)   // 14760 words
#define DEPTH   3           // ring buffers, fills issued 2 ahead
#define BSPLIT  29          // 29*5 = 145 blocks, 1 per SM
#define NT      384         // 3 image-slices x 128 kl-threads = 12 warps
#define SMEM_BYTES (DEPTH*BUFW*4)   // 177,120 B

// Extracted weights: g_w[k*100 + dy*10 + dx]
__device__ float g_w[NK * KHW];

__global__ void extract_kernel(const float* __restrict__ W)
{
    int idx = blockIdx.x * blockDim.x + threadIdx.x;
    if (idx >= NK * KHW) return;
    int k  = idx / KHW;
    int d  = idx - k * KHW;
    int dy = d / 10;
    int dx = d - dy * 10;
    int ki = k / NKW;
    int kj = k - ki * NKW;
    int r  = (ki * 5 + dy) * WPAD + (kj * 5 + dx);
    g_w[idx] = W[(size_t)r * NK + k];
}

__device__ __forceinline__ void cp16(unsigned int dst_smem, const float* src, int src_sz)
{
    asm volatile("cp.async.cg.shared.global [%0], [%1], 16, %2;\n"
                 :: "r"(dst_smem), "l"(src), "r"(src_sz));
}

// ---------------------------------------------------------------------------
// 384 threads = 3 image-slices x 128 kl. Thread (img, kl) holds kl's 100
// weights in registers (57.6K regs total -> fits) and computes image
// (g*3+img) each group. 12 warps/SM = 3 per SMSP hide LDS latency that
// capped all 8-warp variants. Warps are single-image, 32-consecutive-kl ->
// conflict-free x reads at XS=164. 3-buffer cp.async ring, fills 2 ahead.
// ---------------------------------------------------------------------------
__global__ __launch_bounds__(NT, 1)
void lc2d_kernel(const float* __restrict__ x,
                 const float* __restrict__ bias,
                 float* __restrict__ out)
{
    extern __shared__ float xs[];
    const unsigned int xs_base = (unsigned int)__cvta_generic_to_shared(xs);

    const int bx  = blockIdx.x;   // 0..28
    const int ig  = blockIdx.y;   // 0..4
    const int tid = threadIdx.x;  // 0..383

    // zero halo columns once (padded cols -2,-1,130,131 of every staged row)
    for (int idx = tid; idx < DEPTH * HB * XROWS; idx += NT) {
        float* p = &xs[idx * XS];
        p[2] = 0.f; p[3] = 0.f; p[132] = 0.f; p[133] = 0.f;
    }

    const int img = tid >> 7;              // 0..2  (warp w: w/4 = img)
    const int klr = tid & 127;             // 0..127
    const int kl  = klr < KL ? klr : KL - 1;
    const bool tv = klr < KL;
    const int il  = kl / 25;
    const int jj  = kl - il * 25;

    // ---- 100 weights into registers ----
    float4 w4[25];
    {
        const float4* wg = reinterpret_cast<const float4*>(g_w) + (ig * KL + kl) * 25;
        #pragma unroll
        for (int j = 0; j < 25; ++j) w4[j] = __ldg(&wg[j]);
    }
    const float bv = __ldg(&bias[ig * KL + kl]);

    const int r0       = ig * 25 - 2;
    const int nb_total = (BATCH - 1 - bx) / BSPLIT + 1;   // 35 or 36
    const int NG       = (nb_total + HB - 1) / HB;        // 12

    const int xoff = (il * 5) * XS + jj * 5 + 2;

    // fill buffer (hg % DEPTH) with group hg (3 images): 2880 float4
    auto fill = [&](int hg) {
        int buf = hg % DEPTH;
        #pragma unroll
        for (int i = 0; i < 8; ++i) {
            int idx = tid + i * NT;
            if (idx < HB * XROWS * 32) {
                int bl  = idx / (XROWS * 32);
                int rem = idx - bl * (XROWS * 32);
                int rr  = rem >> 5;
                int c4  = rem & 31;
                int t   = hg * HB + bl;
                int r   = r0 + rr;
                bool v  = (t < nb_total) & (r >= 0) & (r < IN_H);
                const float* src = v
                    ? x + (size_t)(bx + t * BSPLIT) * (IN_H * IN_W) + r * IN_W + c4 * 4
                    : x;
                unsigned int dst = xs_base +
                    (unsigned int)(buf * BUFW + bl * IMGW + rr * XS + 4 + c4 * 4) * 4u;
                cp16(dst, src, v ? 16 : 0);
            }
        }
        asm volatile("cp.async.commit_group;\n");
    };

    fill(0);
    fill(1);

    for (int g = 0; g < NG; ++g) {
        if (g + 1 < NG) asm volatile("cp.async.wait_group 1;\n");
        else            asm volatile("cp.async.wait_group 0;\n");
        __syncthreads();

        {
            const float* xp = xs + (g % DEPTH) * BUFW + img * IMGW + xoff;
            // two independent chains (even/odd dx) for this thread's image
            float ae = 0.f, ao = 0.f;
            const float* wf = reinterpret_cast<const float*>(w4);
            #pragma unroll
            for (int dy = 0; dy < 10; ++dy) {
                const float* row = xp + dy * XS;
                const float* wr  = wf + dy * 10;
                #pragma unroll
                for (int dx = 0; dx < 10; dx += 2) {
                    ae = fmaf(row[dx    ], wr[dx    ], ae);
                    ao = fmaf(row[dx + 1], wr[dx + 1], ao);
                }
            }
            int t = g * HB + img;
            if (tv && t < nb_total)
                out[(size_t)(bx + t * BSPLIT) * NK + ig * KL + kl] = ae + ao + bv;
        }
        __syncthreads();

        if (g + 2 < NG) fill(g + 2);
    }
}

// ---------------------------------------------------------------------------
extern "C" void kernel_launch(void* const* d_in, const int* in_sizes, int n_in,
                              void* d_out, int out_size)
{
    const float* x    = (const float*)d_in[0];   // [1024,128,128]
    const float* W    = (const float*)d_in[1];   // [17424,625]
    const float* bias = (const float*)d_in[2];   // [25,25]
    float* out = (float*)d_out;                  // [1024,25,25]

    cudaFuncSetAttribute(lc2d_kernel,
                         cudaFuncAttributeMaxDynamicSharedMemorySize, SMEM_BYTES);

    extract_kernel<<<(NK * KHW + 255) / 256, 256>>>(W);

    dim3 grid(BSPLIT, IGROUPS);
    lc2d_kernel<<<grid, NT, SMEM_BYTES>>>(x, bias, out);
}